// round 8
// baseline (speedup 1.0000x reference)
#include <cuda_runtime.h>
#include <cuda_fp16.h>
#include <cstdint>
#include <math.h>

// Problem constants
#define NB 8
#define LL 12
#define NN 1024
#define HH 32
#define H2 64
#define AF 48
#define NDIM 16

// Scratch (device globals)
__device__ float d_h[8192 * H2];
__device__ float d_scale[H2];
__device__ float d_shift[H2];
__device__ float d_Q[2 * 8192 * HH];
__device__ float d_K[2 * 8192 * HH];
__device__ __half d_gh[16ull * 1024 * 1024];   // 32 MB fp16 graphs

extern __shared__ char dynsmem[];

// ---------------------------------------------------------------------------
#define SWZ128(o) ((o) ^ (((o) >> 3) & 0x70))
#define CP_ASYNC16(dst, src) asm volatile("cp.async.cg.shared.global [%0], [%1], 16;" :: "r"(dst), "l"(src))
#define CP_COMMIT() asm volatile("cp.async.commit_group;" ::: "memory")
#define CP_WAIT1() asm volatile("cp.async.wait_group 1;" ::: "memory")
#define CP_WAIT0() asm volatile("cp.async.wait_group 0;" ::: "memory")
#define LDSM4(r0, r1, r2, r3, addr) \
    asm volatile("ldmatrix.sync.aligned.m8n8.x4.shared.b16 {%0,%1,%2,%3}, [%4];" \
        : "=r"(r0), "=r"(r1), "=r"(r2), "=r"(r3) : "r"(addr))
#define LDSM4T(r0, r1, r2, r3, addr) \
    asm volatile("ldmatrix.sync.aligned.m8n8.x4.trans.shared.b16 {%0,%1,%2,%3}, [%4];" \
        : "=r"(r0), "=r"(r1), "=r"(r2), "=r"(r3) : "r"(addr))

__device__ __forceinline__ uint32_t smem_u32(const void* p) {
    uint32_t a;
    asm("{ .reg .u64 t; cvta.to.shared.u64 t, %1; cvt.u32.u64 %0, t; }" : "=r"(a) : "l"(p));
    return a;
}
__device__ __forceinline__ float ex2(float x) {
    float y;
    asm("ex2.approx.ftz.f32 %0, %1;" : "=f"(y) : "f"(x));
    return y;
}
__device__ __forceinline__ void mma_fp16(float* c, const uint32_t* a, const uint32_t* b) {
    asm volatile(
        "mma.sync.aligned.m16n8k16.row.col.f32.f16.f16.f32 "
        "{%0,%1,%2,%3}, {%4,%5,%6,%7}, {%8,%9}, {%0,%1,%2,%3};"
        : "+f"(c[0]), "+f"(c[1]), "+f"(c[2]), "+f"(c[3])
        : "r"(a[0]), "r"(a[1]), "r"(a[2]), "r"(a[3]), "r"(b[0]), "r"(b[1]));
}

// ---------------------------------------------------------------------------
// Kernel 1: h = relu(X @ W1 + b1)
__global__ void k_h(const float* __restrict__ hd, const float* __restrict__ W1,
                    const float* __restrict__ b1, float* __restrict__ h) {
    __shared__ float sW[LL * H2];
    __shared__ float sb[H2];
    int tid = threadIdx.x;
    for (int i = tid; i < LL * H2; i += 256) sW[i] = W1[i];
    if (tid < H2) sb[tid] = b1[tid];
    __syncthreads();
    int row = blockIdx.x * 4 + (tid >> 6);
    int col = tid & 63;
    int b = row >> 10, n = row & 1023;
    float acc = sb[col];
#pragma unroll
    for (int l = 0; l < LL; l++)
        acc += hd[((size_t)(b * LL + l) << 10) + n] * sW[l * H2 + col];
    h[(size_t)row * H2 + col] = fmaxf(acc, 0.f);
}

// ---------------------------------------------------------------------------
// Kernel 2: BN stats -> folded scale/shift
__global__ void k_stats(const float* __restrict__ h, const float* __restrict__ gamma,
                        const float* __restrict__ beta,
                        float* __restrict__ scale, float* __restrict__ shift) {
    int c = blockIdx.x;
    float s = 0.f, s2 = 0.f;
    for (int r = threadIdx.x; r < 8192; r += 256) {
        float v = h[(size_t)r * H2 + c];
        s += v; s2 += v * v;
    }
    __shared__ float rs[256], rs2[256];
    rs[threadIdx.x] = s; rs2[threadIdx.x] = s2;
    __syncthreads();
    for (int o = 128; o > 0; o >>= 1) {
        if (threadIdx.x < o) { rs[threadIdx.x] += rs[threadIdx.x + o]; rs2[threadIdx.x] += rs2[threadIdx.x + o]; }
        __syncthreads();
    }
    if (threadIdx.x == 0) {
        float mu = rs[0] * (1.f / 8192.f);
        float var = rs2[0] * (1.f / 8192.f) - mu * mu;
        float sc = gamma[c] * rsqrtf(var + 1e-5f);
        scale[c] = sc;
        shift[c] = beta[c] - mu * sc;
    }
}

// ---------------------------------------------------------------------------
// Kernel 3: fused dy + Q/K projections. 16 rows per 128-thread block, 512 blocks.
__global__ void k_dyqk(const float* __restrict__ h, const float* __restrict__ scale,
                       const float* __restrict__ shift, const float* __restrict__ W2,
                       const float* __restrict__ b2,
                       const float* __restrict__ embd, const float* __restrict__ embu,
                       const float* __restrict__ WQ, const float* __restrict__ WK,
                       float* __restrict__ Q, float* __restrict__ K) {
    __shared__ float sW2[H2 * HH];
    __shared__ float sWQ[AF * HH];
    __shared__ float sWK[AF * HH];
    __shared__ float sb2[HH];
    __shared__ float ssc[H2], ssh[H2];
    __shared__ float shh[16][H2];
    __shared__ float sed[16][NDIM], seu[16][NDIM];
    __shared__ float sdy[16][HH];
    int tid = threadIdx.x;
    int row0 = blockIdx.x * 16;
    int n0 = row0 & 1023;

    for (int i = tid; i < H2 * HH; i += 128) sW2[i] = W2[i];
    for (int i = tid; i < AF * HH; i += 128) { sWQ[i] = WQ[i]; sWK[i] = WK[i]; }
    if (tid < HH) sb2[tid] = b2[tid];
    if (tid < H2) { ssc[tid] = scale[tid]; ssh[tid] = shift[tid]; }
    for (int i = tid; i < 16 * NDIM; i += 128) {
        int r = i >> 4, k = i & 15;
        sed[r][k] = embd[(n0 + r) * NDIM + k];
        seu[r][k] = embu[(n0 + r) * NDIM + k];
    }
    __syncthreads();
    for (int i = tid; i < 16 * H2; i += 128) {
        int r = i >> 6, c = i & 63;
        shh[r][c] = h[(size_t)(row0 + r) * H2 + c] * ssc[c] + ssh[c];
    }
    __syncthreads();

    int rr = tid >> 5, c = tid & 31;
#pragma unroll
    for (int p = 0; p < 4; p++) {
        int r = p * 4 + rr;
        float acc = sb2[c];
#pragma unroll
        for (int k = 0; k < H2; k++) acc += shh[r][k] * sW2[k * HH + c];
        sdy[r][c] = acc;
    }
    __syncthreads();

#pragma unroll
    for (int p = 0; p < 4; p++) {
        int r = p * 4 + rr;
        float q0 = 0.f, k0 = 0.f;
#pragma unroll
        for (int k = 0; k < HH; k++) {
            float f = sdy[r][k];
            q0 += f * sWQ[k * HH + c];
            k0 += f * sWK[k * HH + c];
        }
        float qd = q0, qu = q0, kd = k0, ku = k0;
#pragma unroll
        for (int k = 0; k < NDIM; k++) {
            float wq = sWQ[(HH + k) * HH + c];
            float wk = sWK[(HH + k) * HH + c];
            qd += sed[r][k] * wq; qu += seu[r][k] * wq;
            kd += sed[r][k] * wk; ku += seu[r][k] * wk;
        }
        size_t od = (size_t)(row0 + r) * HH + c;
        size_t ou = (size_t)(8192 + row0 + r) * HH + c;
        Q[od] = qd; Q[ou] = qu;
        K[od] = kd; K[ou] = ku;
    }
}

// ---------------------------------------------------------------------------
// Kernel 4: attention. K columns loaded straight from global (L2-resident);
// exp+mask fused into phase 1 with running row-sums; phase 2 rescales+writes.
// smem: sQ 1KB + sV 32KB + sRed 256B -> ~34KB, ~4 CTAs/SM.
#define PSC 0.25507600725815733f   // (1/sqrt(32)) * log2(e)
__global__ void __launch_bounds__(256, 4)
k_attn(const float* __restrict__ Q, const float* __restrict__ K,
       const float* __restrict__ adj0, const float* __restrict__ adj1,
       __half* __restrict__ gh, float* __restrict__ out) {
    float* smemf = (float*)dynsmem;
    float* sQ = smemf;                 // 256
    float* sV = smemf + 256;           // 8 * 1024
    float* sRed = smemf + 256 + 8192;  // 8 warps x 8 rows
    int tid = threadIdx.x;
    int w = tid >> 5, lane = tid & 31;
    int blk = blockIdx.x;
    int e = blk >> 10;
    int rb = blk & 1023;
    int b = rb >> 7;
    int row0 = (rb & 127) * 8;
    const float* adj = e ? adj1 : adj0;
    size_t qbase = ((size_t)e * 8192 + b * 1024 + row0) * HH;
    size_t kbase = ((size_t)e * 8192 + b * 1024) * HH;
    sQ[tid] = Q[qbase + tid];
    __syncthreads();

    float psum[8];
#pragma unroll
    for (int r = 0; r < 8; r++) psum[r] = 0.f;

#pragma unroll
    for (int t = 0; t < 4; t++) {
        int m = t * 256 + tid;
        float4 kv[8];
#pragma unroll
        for (int q = 0; q < 8; q++)
            kv[q] = *(const float4*)&K[kbase + (size_t)m * HH + q * 4];
#pragma unroll
        for (int r = 0; r < 8; r++) {
            float acc = 0.f;
#pragma unroll
            for (int q = 0; q < 8; q++) {
                float4 qv = *(const float4*)&sQ[r * 32 + q * 4];
                acc += qv.x * kv[q].x + qv.y * kv[q].y + qv.z * kv[q].z + qv.w * kv[q].w;
            }
            float e2 = ex2(acc * PSC);
            float a = adj[(size_t)(row0 + r) * 1024 + m];
            float v = e2 * a + e2 * 1e-7f;
            sV[r * 1024 + m] = v;
            psum[r] += v;
        }
    }
    // row-sum reduce: warp shuffle then cross-warp via smem
#pragma unroll
    for (int r = 0; r < 8; r++) {
        float s = psum[r];
        for (int o = 16; o > 0; o >>= 1) s += __shfl_xor_sync(0xffffffffu, s, o);
        if (lane == 0) sRed[w * 8 + r] = s;
    }
    __syncthreads();
    float inv[8];
#pragma unroll
    for (int r = 0; r < 8; r++) {
        float s = 0.f;
#pragma unroll
        for (int ww = 0; ww < 8; ww++) s += sRed[ww * 8 + r];
        float iv = 1.f / s;
        inv[r] = isfinite(iv) ? iv : 0.f;
    }

    size_t gbase = ((size_t)e * 8192 + b * 1024) * 1024;
    size_t obase = (size_t)(2 * e) * (16ull << 20) + ((size_t)b << 10) * 2048;
#pragma unroll
    for (int t = 0; t < 4; t++) {
        int m = t * 256 + tid;
#pragma unroll
        for (int r = 0; r < 8; r++) {
            int n = row0 + r;
            float val = sV[r * 1024 + m] * inv[r];
            gh[gbase + (size_t)n * 1024 + m] = __float2half_rn(val);
            float vo = (m == n) ? 0.f : val;
            size_t rowb = obase + (size_t)n * 2048;
            out[rowb + m] = vo;
            out[rowb + 1024 + m] = vo;
        }
    }
}

// ---------------------------------------------------------------------------
// Kernel 5: fp16 mma.sync GEMM. Block tile 128x128, 128 threads (4 warps,
// each 64x64), k-chunk 64, cp.async double buffering, 2 CTAs/SM.
#define A_BYTES 16384
#define B_PITCH 272
#define B_BYTES (64 * B_PITCH)
#define GEMM_SMEM (2 * A_BYTES + 2 * B_BYTES)

__global__ void __launch_bounds__(128, 2)
k_gemm_fp16(const __half* __restrict__ gh, float* __restrict__ out) {
    char* smem = dynsmem;
    uint32_t sb = smem_u32(smem);
    const uint32_t AOFF[2] = {0u, A_BYTES};
    const uint32_t BOFF[2] = {2 * A_BYTES, 2 * A_BYTES + B_BYTES};
    int tid = threadIdx.x;
    int eb = blockIdx.z;
    int tm = blockIdx.y * 128, tn = blockIdx.x * 128;
    size_t base = (size_t)eb << 20;

    int wid = tid >> 5, lane = tid & 31;
    int gid = lane >> 2, tig = lane & 3;
    int warp_m = wid & 1, warp_n = wid >> 1;
    int rb0 = warp_m * 64, cb0 = warp_n * 64;

    float acc[4][8][4];
#pragma unroll
    for (int i = 0; i < 4; i++)
#pragma unroll
        for (int j = 0; j < 8; j++)
#pragma unroll
            for (int q = 0; q < 4; q++) acc[i][j][q] = 0.f;

    int lr = lane & 7;
    int lm = (lane >> 3) & 1;
    int lk = lane >> 4;

    auto load_chunk = [&](int c, int buf) {
        int k0 = c * 64;
#pragma unroll
        for (int q = 0; q < 8; q++) {
            int idx = tid + q * 128;
            int r = idx >> 3, s = idx & 7;
            uint32_t dst = sb + AOFF[buf] + SWZ128((uint32_t)(r * 128 + s * 16));
            const __half* src = gh + base + ((size_t)(tm + r) << 10) + k0 + s * 8;
            CP_ASYNC16(dst, src);
        }
#pragma unroll
        for (int q = 0; q < 8; q++) {
            int idx = tid + q * 128;
            int r = idx >> 4, s = idx & 15;
            uint32_t dst = sb + BOFF[buf] + (uint32_t)(r * B_PITCH + s * 16);
            const __half* src = gh + base + ((size_t)(k0 + r) << 10) + tn + s * 8;
            CP_ASYNC16(dst, src);
        }
        CP_COMMIT();
    };

    load_chunk(0, 0);
    for (int c = 0; c < 16; c++) {
        int buf = c & 1;
        if (c < 15) { load_chunk(c + 1, buf ^ 1); CP_WAIT1(); }
        else        { CP_WAIT0(); }
        __syncthreads();
        uint32_t abase = sb + AOFF[buf];
        uint32_t bbase = sb + BOFF[buf];
#pragma unroll
        for (int kk = 0; kk < 64; kk += 16) {
            uint32_t af[4][4], bf[4][4];
#pragma unroll
            for (int mt = 0; mt < 4; mt++) {
                int m = rb0 + mt * 16 + lm * 8 + lr;
                uint32_t addr = abase + SWZ128((uint32_t)(m * 128 + kk * 2 + lk * 16));
                LDSM4(af[mt][0], af[mt][1], af[mt][2], af[mt][3], addr);
            }
#pragma unroll
            for (int nt2 = 0; nt2 < 4; nt2++) {
                int krow = kk + lm * 8 + lr;
                int n = cb0 + nt2 * 16 + lk * 8;
                uint32_t addr = bbase + (uint32_t)(krow * B_PITCH + n * 2);
                LDSM4T(bf[nt2][0], bf[nt2][1], bf[nt2][2], bf[nt2][3], addr);
            }
#pragma unroll
            for (int mt = 0; mt < 4; mt++)
#pragma unroll
                for (int nt = 0; nt < 8; nt++)
                    mma_fp16(acc[mt][nt], af[mt], &bf[nt >> 1][(nt & 1) * 2]);
        }
        __syncthreads();
    }

    int e = eb >> 3, b_ = eb & 7;
    size_t obase = (size_t)(2 * e + 1) * (16ull << 20) + ((size_t)b_ << 10) * 2048;
#pragma unroll
    for (int mt = 0; mt < 4; mt++) {
#pragma unroll
        for (int half = 0; half < 2; half++) {
            int i = tm + rb0 + mt * 16 + gid + half * 8;
            size_t rowb = obase + (size_t)i * 2048;
#pragma unroll
            for (int nt = 0; nt < 8; nt++) {
                int j = tn + cb0 + nt * 8 + tig * 2;
                float2 v;
                v.x = acc[mt][nt][half * 2 + 0];
                v.y = acc[mt][nt][half * 2 + 1];
                if (i == j) v.x = 0.f;
                if (i == j + 1) v.y = 0.f;
                *(float2*)&out[rowb + j] = v;
                *(float2*)&out[rowb + 1024 + j] = v;
            }
        }
    }
}

// ---------------------------------------------------------------------------
extern "C" void kernel_launch(void* const* d_in, const int* in_sizes, int n_in,
                              void* d_out, int out_size) {
    const float* hd   = (const float*)d_in[0];
    const float* embd = (const float*)d_in[1];
    const float* embu = (const float*)d_in[2];
    const float* adj0 = (const float*)d_in[3];
    const float* adj1 = (const float*)d_in[4];
    const float* W1   = (const float*)d_in[5];
    const float* b1   = (const float*)d_in[6];
    const float* gam  = (const float*)d_in[7];
    const float* bet  = (const float*)d_in[8];
    const float* W2   = (const float*)d_in[9];
    const float* b2   = (const float*)d_in[10];
    const float* WQ   = (const float*)d_in[11];
    const float* WK   = (const float*)d_in[12];
    float* out = (float*)d_out;

    float *ph, *psc, *psh, *pQ, *pK;
    __half* pgh;
    cudaGetSymbolAddress((void**)&ph,  d_h);
    cudaGetSymbolAddress((void**)&psc, d_scale);
    cudaGetSymbolAddress((void**)&psh, d_shift);
    cudaGetSymbolAddress((void**)&pQ,  d_Q);
    cudaGetSymbolAddress((void**)&pK,  d_K);
    cudaGetSymbolAddress((void**)&pgh, d_gh);

    k_h<<<2048, 256>>>(hd, W1, b1, ph);
    k_stats<<<64, 256>>>(ph, gam, bet, psc, psh);
    k_dyqk<<<512, 128>>>(ph, psc, psh, W2, b2, embd, embu, WQ, WK, pQ, pK);

    int attn_smem = (256 + 8 * 1024 + 64) * (int)sizeof(float);
    cudaFuncSetAttribute(k_attn, cudaFuncAttributeMaxDynamicSharedMemorySize, attn_smem);
    k_attn<<<2048, 256, attn_smem>>>(pQ, pK, adj0, adj1, pgh, out);

    cudaFuncSetAttribute(k_gemm_fp16, cudaFuncAttributeMaxDynamicSharedMemorySize, GEMM_SMEM);
    dim3 ggrid(8, 8, 16);
    k_gemm_fp16<<<ggrid, 128, GEMM_SMEM>>>(pgh, out);
}

// round 9
// speedup vs baseline: 3.1063x; 3.1063x over previous
#include <cuda_runtime.h>
#include <cuda_fp16.h>
#include <cstdint>
#include <math.h>

// Problem constants
#define NB 8
#define LL 12
#define NN 1024
#define HH 32
#define H2 64
#define AF 48
#define NDIM 16

// Scratch (device globals)
__device__ float d_h[8192 * H2];
__device__ float d_scale[H2];
__device__ float d_shift[H2];
__device__ float d_Q[2 * 8192 * HH];
__device__ float d_K[2 * 8192 * HH];
__device__ __half d_gh[16ull * 1024 * 1024];   // 32 MB fp16 graphs

extern __shared__ char dynsmem[];

// ---------------------------------------------------------------------------
#define SWZ128(o) ((o) ^ (((o) >> 3) & 0x70))
#define CP_ASYNC16(dst, src) asm volatile("cp.async.cg.shared.global [%0], [%1], 16;" :: "r"(dst), "l"(src))
#define CP_COMMIT() asm volatile("cp.async.commit_group;" ::: "memory")
#define CP_WAIT1() asm volatile("cp.async.wait_group 1;" ::: "memory")
#define CP_WAIT0() asm volatile("cp.async.wait_group 0;" ::: "memory")
#define LDSM4(r0, r1, r2, r3, addr) \
    asm volatile("ldmatrix.sync.aligned.m8n8.x4.shared.b16 {%0,%1,%2,%3}, [%4];" \
        : "=r"(r0), "=r"(r1), "=r"(r2), "=r"(r3) : "r"(addr))
#define LDSM4T(r0, r1, r2, r3, addr) \
    asm volatile("ldmatrix.sync.aligned.m8n8.x4.trans.shared.b16 {%0,%1,%2,%3}, [%4];" \
        : "=r"(r0), "=r"(r1), "=r"(r2), "=r"(r3) : "r"(addr))

__device__ __forceinline__ uint32_t smem_u32(const void* p) {
    uint32_t a;
    asm("{ .reg .u64 t; cvta.to.shared.u64 t, %1; cvt.u32.u64 %0, t; }" : "=r"(a) : "l"(p));
    return a;
}
__device__ __forceinline__ float ex2(float x) {
    float y;
    asm("ex2.approx.ftz.f32 %0, %1;" : "=f"(y) : "f"(x));
    return y;
}
__device__ __forceinline__ void mma_fp16(float* c, const uint32_t* a, const uint32_t* b) {
    asm volatile(
        "mma.sync.aligned.m16n8k16.row.col.f32.f16.f16.f32 "
        "{%0,%1,%2,%3}, {%4,%5,%6,%7}, {%8,%9}, {%0,%1,%2,%3};"
        : "+f"(c[0]), "+f"(c[1]), "+f"(c[2]), "+f"(c[3])
        : "r"(a[0]), "r"(a[1]), "r"(a[2]), "r"(a[3]), "r"(b[0]), "r"(b[1]));
}

// ---------------------------------------------------------------------------
// Kernel 1: h = relu(X @ W1 + b1)
__global__ void k_h(const float* __restrict__ hd, const float* __restrict__ W1,
                    const float* __restrict__ b1, float* __restrict__ h) {
    __shared__ float sW[LL * H2];
    __shared__ float sb[H2];
    int tid = threadIdx.x;
    for (int i = tid; i < LL * H2; i += 256) sW[i] = W1[i];
    if (tid < H2) sb[tid] = b1[tid];
    __syncthreads();
    int row = blockIdx.x * 4 + (tid >> 6);
    int col = tid & 63;
    int b = row >> 10, n = row & 1023;
    float acc = sb[col];
#pragma unroll
    for (int l = 0; l < LL; l++)
        acc += hd[((size_t)(b * LL + l) << 10) + n] * sW[l * H2 + col];
    h[(size_t)row * H2 + col] = fmaxf(acc, 0.f);
}

// ---------------------------------------------------------------------------
// Kernel 2: BN stats -> folded scale/shift
__global__ void k_stats(const float* __restrict__ h, const float* __restrict__ gamma,
                        const float* __restrict__ beta,
                        float* __restrict__ scale, float* __restrict__ shift) {
    int c = blockIdx.x;
    float s = 0.f, s2 = 0.f;
    for (int r = threadIdx.x; r < 8192; r += 256) {
        float v = h[(size_t)r * H2 + c];
        s += v; s2 += v * v;
    }
    __shared__ float rs[256], rs2[256];
    rs[threadIdx.x] = s; rs2[threadIdx.x] = s2;
    __syncthreads();
    for (int o = 128; o > 0; o >>= 1) {
        if (threadIdx.x < o) { rs[threadIdx.x] += rs[threadIdx.x + o]; rs2[threadIdx.x] += rs2[threadIdx.x + o]; }
        __syncthreads();
    }
    if (threadIdx.x == 0) {
        float mu = rs[0] * (1.f / 8192.f);
        float var = rs2[0] * (1.f / 8192.f) - mu * mu;
        float sc = gamma[c] * rsqrtf(var + 1e-5f);
        scale[c] = sc;
        shift[c] = beta[c] - mu * sc;
    }
}

// ---------------------------------------------------------------------------
// Kernel 3: fused dy + Q/K projections. 16 rows per 128-thread block, 512 blocks.
__global__ void k_dyqk(const float* __restrict__ h, const float* __restrict__ scale,
                       const float* __restrict__ shift, const float* __restrict__ W2,
                       const float* __restrict__ b2,
                       const float* __restrict__ embd, const float* __restrict__ embu,
                       const float* __restrict__ WQ, const float* __restrict__ WK,
                       float* __restrict__ Q, float* __restrict__ K) {
    __shared__ float sW2[H2 * HH];
    __shared__ float sWQ[AF * HH];
    __shared__ float sWK[AF * HH];
    __shared__ float sb2[HH];
    __shared__ float ssc[H2], ssh[H2];
    __shared__ float shh[16][H2];
    __shared__ float sed[16][NDIM], seu[16][NDIM];
    __shared__ float sdy[16][HH];
    int tid = threadIdx.x;
    int row0 = blockIdx.x * 16;
    int n0 = row0 & 1023;

    for (int i = tid; i < H2 * HH; i += 128) sW2[i] = W2[i];
    for (int i = tid; i < AF * HH; i += 128) { sWQ[i] = WQ[i]; sWK[i] = WK[i]; }
    if (tid < HH) sb2[tid] = b2[tid];
    if (tid < H2) { ssc[tid] = scale[tid]; ssh[tid] = shift[tid]; }
    for (int i = tid; i < 16 * NDIM; i += 128) {
        int r = i >> 4, k = i & 15;
        sed[r][k] = embd[(n0 + r) * NDIM + k];
        seu[r][k] = embu[(n0 + r) * NDIM + k];
    }
    __syncthreads();
    for (int i = tid; i < 16 * H2; i += 128) {
        int r = i >> 6, c = i & 63;
        shh[r][c] = h[(size_t)(row0 + r) * H2 + c] * ssc[c] + ssh[c];
    }
    __syncthreads();

    int rr = tid >> 5, c = tid & 31;
#pragma unroll
    for (int p = 0; p < 4; p++) {
        int r = p * 4 + rr;
        float acc = sb2[c];
#pragma unroll
        for (int k = 0; k < H2; k++) acc += shh[r][k] * sW2[k * HH + c];
        sdy[r][c] = acc;
    }
    __syncthreads();

#pragma unroll
    for (int p = 0; p < 4; p++) {
        int r = p * 4 + rr;
        float q0 = 0.f, k0 = 0.f;
#pragma unroll
        for (int k = 0; k < HH; k++) {
            float f = sdy[r][k];
            q0 += f * sWQ[k * HH + c];
            k0 += f * sWK[k * HH + c];
        }
        float qd = q0, qu = q0, kd = k0, ku = k0;
#pragma unroll
        for (int k = 0; k < NDIM; k++) {
            float wq = sWQ[(HH + k) * HH + c];
            float wk = sWK[(HH + k) * HH + c];
            qd += sed[r][k] * wq; qu += seu[r][k] * wq;
            kd += sed[r][k] * wk; ku += seu[r][k] * wk;
        }
        size_t od = (size_t)(row0 + r) * HH + c;
        size_t ou = (size_t)(8192 + row0 + r) * HH + c;
        Q[od] = qd; Q[ou] = qu;
        K[od] = kd; K[ou] = ku;
    }
}

// ---------------------------------------------------------------------------
// Kernel 4: attention, staged-K (R7 structure), 16 rows / 512 threads per CTA.
// smem: sQ 2KB + sKT 32x257 (32.1KB) + sE 64KB = ~98KB -> 2 CTAs/SM, 50% occ.
#define KT_P 257
#define PSC 0.25507600725815733f   // (1/sqrt(32)) * log2(e)
__global__ void __launch_bounds__(512, 2)
k_attn(const float* __restrict__ Q, const float* __restrict__ K,
       const float* __restrict__ adj0, const float* __restrict__ adj1,
       __half* __restrict__ gh, float* __restrict__ out) {
    float* smemf = (float*)dynsmem;
    float* sQ  = smemf;                       // 512
    float* sKT = smemf + 512;                 // 32 * 257
    float* sE  = smemf + 512 + 32 * KT_P;     // 16 * 1024
    int tid = threadIdx.x;
    int blk = blockIdx.x;                     // 0..1023
    int e = blk >> 9;
    int rb = blk & 511;
    int b = rb >> 6;
    int row0 = (rb & 63) * 16;
    const float* adj = e ? adj1 : adj0;
    size_t qbase = ((size_t)e * 8192 + b * 1024 + row0) * HH;
    size_t kbase = ((size_t)e * 8192 + b * 1024) * HH;
    sQ[tid] = Q[qbase + tid];
    int tg = tid >> 8;        // 0/1 -> rows 0-7 / 8-15
    int tl = tid & 255;       // m within chunk
    int r0 = tg * 8;

    for (int t = 0; t < 4; t++) {
        __syncthreads();
        for (int i = tid; i < 8192; i += 512) {
            int r = i >> 5, c = i & 31;     // r: m-in-chunk, c: k
            sKT[c * KT_P + r] = K[kbase + (size_t)t * 8192 + i];
        }
        __syncthreads();
        float kreg[32];
#pragma unroll
        for (int k = 0; k < 32; k++) kreg[k] = sKT[k * KT_P + tl];
#pragma unroll
        for (int r = 0; r < 8; r++) {
            float acc = 0.f;
#pragma unroll
            for (int q4 = 0; q4 < 8; q4++) {
                float4 qv = *(const float4*)&sQ[(r0 + r) * 32 + q4 * 4];
                acc += qv.x * kreg[q4 * 4 + 0];
                acc += qv.y * kreg[q4 * 4 + 1];
                acc += qv.z * kreg[q4 * 4 + 2];
                acc += qv.w * kreg[q4 * 4 + 3];
            }
            sE[(r0 + r) * 1024 + t * 256 + tl] = acc * PSC;
        }
    }
    __syncthreads();

    int w = tid >> 5, lane = tid & 31;      // w = 0..15 -> row
    int n = row0 + w;
    float v[32];
    float sum = 0.f;
#pragma unroll
    for (int i = 0; i < 32; i++) {
        int m = i * 32 + lane;
        float e2 = ex2(sE[w * 1024 + m]);
        float a = adj[(size_t)n * 1024 + m];
        float vv = e2 * a + e2 * 1e-7f;
        v[i] = vv;
        sum += vv;
    }
    for (int o = 16; o > 0; o >>= 1) sum += __shfl_xor_sync(0xffffffffu, sum, o);
    float inv = 1.f / sum;
    if (!isfinite(inv)) inv = 0.f;

    size_t gbase = ((size_t)e * 8192 + b * 1024 + n) * 1024;
    size_t obase = (size_t)(2 * e) * (16ull << 20) + ((size_t)b * 1024 + n) * 2048;
#pragma unroll
    for (int i = 0; i < 32; i++) {
        int m = i * 32 + lane;
        float val = v[i] * inv;
        gh[gbase + m] = __float2half_rn(val);
        float vo = (m == n) ? 0.f : val;
        out[obase + m] = vo;
        out[obase + 1024 + m] = vo;
    }
}

// ---------------------------------------------------------------------------
// Kernel 5: fp16 mma.sync GEMM. Block tile 128x128, 128 threads (4 warps,
// each 64x64), k-chunk 64, cp.async double buffering, 2 CTAs/SM.
#define A_BYTES 16384
#define B_PITCH 272
#define B_BYTES (64 * B_PITCH)
#define GEMM_SMEM (2 * A_BYTES + 2 * B_BYTES)

__global__ void __launch_bounds__(128, 2)
k_gemm_fp16(const __half* __restrict__ gh, float* __restrict__ out) {
    char* smem = dynsmem;
    uint32_t sb = smem_u32(smem);
    const uint32_t AOFF[2] = {0u, A_BYTES};
    const uint32_t BOFF[2] = {2 * A_BYTES, 2 * A_BYTES + B_BYTES};
    int tid = threadIdx.x;
    int eb = blockIdx.z;
    int tm = blockIdx.y * 128, tn = blockIdx.x * 128;
    size_t base = (size_t)eb << 20;

    int wid = tid >> 5, lane = tid & 31;
    int gid = lane >> 2, tig = lane & 3;
    int warp_m = wid & 1, warp_n = wid >> 1;
    int rb0 = warp_m * 64, cb0 = warp_n * 64;

    float acc[4][8][4];
#pragma unroll
    for (int i = 0; i < 4; i++)
#pragma unroll
        for (int j = 0; j < 8; j++)
#pragma unroll
            for (int q = 0; q < 4; q++) acc[i][j][q] = 0.f;

    int lr = lane & 7;
    int lm = (lane >> 3) & 1;
    int lk = lane >> 4;

    auto load_chunk = [&](int c, int buf) {
        int k0 = c * 64;
#pragma unroll
        for (int q = 0; q < 8; q++) {
            int idx = tid + q * 128;
            int r = idx >> 3, s = idx & 7;
            uint32_t dst = sb + AOFF[buf] + SWZ128((uint32_t)(r * 128 + s * 16));
            const __half* src = gh + base + ((size_t)(tm + r) << 10) + k0 + s * 8;
            CP_ASYNC16(dst, src);
        }
#pragma unroll
        for (int q = 0; q < 8; q++) {
            int idx = tid + q * 128;
            int r = idx >> 4, s = idx & 15;
            uint32_t dst = sb + BOFF[buf] + (uint32_t)(r * B_PITCH + s * 16);
            const __half* src = gh + base + ((size_t)(k0 + r) << 10) + tn + s * 8;
            CP_ASYNC16(dst, src);
        }
        CP_COMMIT();
    };

    load_chunk(0, 0);
    for (int c = 0; c < 16; c++) {
        int buf = c & 1;
        if (c < 15) { load_chunk(c + 1, buf ^ 1); CP_WAIT1(); }
        else        { CP_WAIT0(); }
        __syncthreads();
        uint32_t abase = sb + AOFF[buf];
        uint32_t bbase = sb + BOFF[buf];
#pragma unroll
        for (int kk = 0; kk < 64; kk += 16) {
            uint32_t af[4][4], bf[4][4];
#pragma unroll
            for (int mt = 0; mt < 4; mt++) {
                int m = rb0 + mt * 16 + lm * 8 + lr;
                uint32_t addr = abase + SWZ128((uint32_t)(m * 128 + kk * 2 + lk * 16));
                LDSM4(af[mt][0], af[mt][1], af[mt][2], af[mt][3], addr);
            }
#pragma unroll
            for (int nt2 = 0; nt2 < 4; nt2++) {
                int krow = kk + lm * 8 + lr;
                int n = cb0 + nt2 * 16 + lk * 8;
                uint32_t addr = bbase + (uint32_t)(krow * B_PITCH + n * 2);
                LDSM4T(bf[nt2][0], bf[nt2][1], bf[nt2][2], bf[nt2][3], addr);
            }
#pragma unroll
            for (int mt = 0; mt < 4; mt++)
#pragma unroll
                for (int nt = 0; nt < 8; nt++)
                    mma_fp16(acc[mt][nt], af[mt], &bf[nt >> 1][(nt & 1) * 2]);
        }
        __syncthreads();
    }

    int e = eb >> 3, b_ = eb & 7;
    size_t obase = (size_t)(2 * e + 1) * (16ull << 20) + ((size_t)b_ << 10) * 2048;
#pragma unroll
    for (int mt = 0; mt < 4; mt++) {
#pragma unroll
        for (int half = 0; half < 2; half++) {
            int i = tm + rb0 + mt * 16 + gid + half * 8;
            size_t rowb = obase + (size_t)i * 2048;
#pragma unroll
            for (int nt = 0; nt < 8; nt++) {
                int j = tn + cb0 + nt * 8 + tig * 2;
                float2 v;
                v.x = acc[mt][nt][half * 2 + 0];
                v.y = acc[mt][nt][half * 2 + 1];
                if (i == j) v.x = 0.f;
                if (i == j + 1) v.y = 0.f;
                *(float2*)&out[rowb + j] = v;
                *(float2*)&out[rowb + 1024 + j] = v;
            }
        }
    }
}

// ---------------------------------------------------------------------------
extern "C" void kernel_launch(void* const* d_in, const int* in_sizes, int n_in,
                              void* d_out, int out_size) {
    const float* hd   = (const float*)d_in[0];
    const float* embd = (const float*)d_in[1];
    const float* embu = (const float*)d_in[2];
    const float* adj0 = (const float*)d_in[3];
    const float* adj1 = (const float*)d_in[4];
    const float* W1   = (const float*)d_in[5];
    const float* b1   = (const float*)d_in[6];
    const float* gam  = (const float*)d_in[7];
    const float* bet  = (const float*)d_in[8];
    const float* W2   = (const float*)d_in[9];
    const float* b2   = (const float*)d_in[10];
    const float* WQ   = (const float*)d_in[11];
    const float* WK   = (const float*)d_in[12];
    float* out = (float*)d_out;

    float *ph, *psc, *psh, *pQ, *pK;
    __half* pgh;
    cudaGetSymbolAddress((void**)&ph,  d_h);
    cudaGetSymbolAddress((void**)&psc, d_scale);
    cudaGetSymbolAddress((void**)&psh, d_shift);
    cudaGetSymbolAddress((void**)&pQ,  d_Q);
    cudaGetSymbolAddress((void**)&pK,  d_K);
    cudaGetSymbolAddress((void**)&pgh, d_gh);

    k_h<<<2048, 256>>>(hd, W1, b1, ph);
    k_stats<<<64, 256>>>(ph, gam, bet, psc, psh);
    k_dyqk<<<512, 128>>>(ph, psc, psh, W2, b2, embd, embu, WQ, WK, pQ, pK);

    int attn_smem = (512 + 32 * KT_P + 16 * 1024) * (int)sizeof(float);
    cudaFuncSetAttribute(k_attn, cudaFuncAttributeMaxDynamicSharedMemorySize, attn_smem);
    k_attn<<<1024, 512, attn_smem>>>(pQ, pK, adj0, adj1, pgh, out);

    cudaFuncSetAttribute(k_gemm_fp16, cudaFuncAttributeMaxDynamicSharedMemorySize, GEMM_SMEM);
    dim3 ggrid(8, 8, 16);
    k_gemm_fp16<<<ggrid, 128, GEMM_SMEM>>>(pgh, out);
}